// round 9
// baseline (speedup 1.0000x reference)
#include <cuda_runtime.h>
#include <math.h>
#include <complex>

// ---------------------------------------------------------------------------
// Problem constants
// ---------------------------------------------------------------------------
#define MAX_E 256000

// Flat CG storage, row-major (a*(2l2+1)+b)*(2l3+1)+c, 11 paths concatenated.
struct CGParams { float cg[363]; };

#define O000 0
#define O110 1
#define O220 10
#define O011 35
#define O101 44
#define O121 53
#define O211 98
#define O022 143
#define O112 168
#define O202 213
#define O222 238

// Per-edge selfmix scratch (channel-independent part of sph_linear)
__device__ float g_Za[MAX_E * 9];
__device__ float g_Zb[MAX_E * 9];

// sqrt(2*l3+1)/sqrt(npaths(l3)):  l3=0: 1/sqrt(3); l3=1: sqrt(3)/2; l3=2: sqrt(5)/2
#define CN0 0.57735026918962576f
#define CN1 0.86602540378443865f
#define CN2 1.11803398874989485f

__device__ __forceinline__ int muv(int i, int L) { return i < L ? L - i : i - L; }

// z[c] += w * sum_{a,b} cg[a,b,c] * x[a] * y[b], with compile-time sparsity
// guard (real-CG nonzeros satisfy mu_c in {mu_a+mu_b, |mu_a-mu_b|}).
template <int L1, int L2, int L3>
__device__ __forceinline__ void tp_acc(const float* x, const float* y,
                                       const float* cg, float w, float* z) {
    float zp[2 * L3 + 1];
#pragma unroll
    for (int c = 0; c < 2 * L3 + 1; ++c) zp[c] = 0.f;
#pragma unroll
    for (int a = 0; a < 2 * L1 + 1; ++a) {
#pragma unroll
        for (int b = 0; b < 2 * L2 + 1; ++b) {
            float p = x[a] * y[b];
#pragma unroll
            for (int c = 0; c < 2 * L3 + 1; ++c) {
                const int mua = muv(a, L1), mub = muv(b, L2), muc = muv(c, L3);
                const int dmu = mua > mub ? mua - mub : mub - mua;
                if (muc == mua + mub || muc == dmu)
                    zp[c] = fmaf(cg[(a * (2 * L2 + 1) + b) * (2 * L3 + 1) + c], p, zp[c]);
            }
        }
    }
#pragma unroll
    for (int c = 0; c < 2 * L3 + 1; ++c) z[c] = fmaf(w, zp[c], z[c]);
}

// Selfmix on one 9-vector (cin = 1)
__device__ __forceinline__ void selfmix1(const float* Y, const float* cg,
                                         const float* w0, const float* w1,
                                         const float* w2, float b0,
                                         const float* k, float* Z) {
#pragma unroll
    for (int m = 0; m < 9; ++m) Z[m] = 0.f;
    tp_acc<0, 0, 0>(Y,     Y,     cg + O000, w0[0] * CN0, Z);
    tp_acc<1, 1, 0>(Y + 1, Y + 1, cg + O110, w0[1] * CN0, Z);
    tp_acc<2, 2, 0>(Y + 4, Y + 4, cg + O220, w0[2] * CN0, Z);
    tp_acc<0, 1, 1>(Y,     Y + 1, cg + O011, w1[0] * CN1, Z + 1);
    tp_acc<1, 0, 1>(Y + 1, Y,     cg + O101, w1[1] * CN1, Z + 1);
    tp_acc<1, 2, 1>(Y + 1, Y + 4, cg + O121, w1[2] * CN1, Z + 1);
    tp_acc<2, 1, 1>(Y + 4, Y + 1, cg + O211, w1[3] * CN1, Z + 1);
    tp_acc<0, 2, 2>(Y,     Y + 4, cg + O022, w2[0] * CN2, Z + 4);
    tp_acc<1, 1, 2>(Y + 1, Y + 1, cg + O112, w2[1] * CN2, Z + 4);
    tp_acc<2, 0, 2>(Y + 4, Y,     cg + O202, w2[2] * CN2, Z + 4);
    tp_acc<2, 2, 2>(Y + 4, Y + 4, cg + O222, w2[3] * CN2, Z + 4);
    Z[0] += b0 + k[0] * Y[0];
#pragma unroll
    for (int m = 1; m < 4; ++m) Z[m] += k[1] * Y[m];
#pragma unroll
    for (int m = 4; m < 9; ++m) Z[m] += k[2] * Y[m];
}

// ---------------------------------------------------------------------------
// Kernel 1: per-edge selfmix of Y_edge, both branches
// ---------------------------------------------------------------------------
__global__ void zprep_kernel(const float* __restrict__ Y_edge,
                             const float* w0a, const float* w1a, const float* w2a,
                             const float* b0a, const float* ka,
                             const float* w0b, const float* w1b, const float* w2b,
                             const float* b0b, const float* kb,
                             int E, CGParams P) {
    int e = blockIdx.x * blockDim.x + threadIdx.x;
    if (e >= E) return;
    float Y[9];
#pragma unroll
    for (int m = 0; m < 9; ++m) Y[m] = Y_edge[(size_t)e * 9 + m];

    float Z[9];
    {
        float w0[3] = {w0a[0], w0a[1], w0a[2]};
        float w1[4] = {w1a[0], w1a[1], w1a[2], w1a[3]};
        float w2[4] = {w2a[0], w2a[1], w2a[2], w2a[3]};
        float kk[3] = {ka[0], ka[1], ka[2]};
        selfmix1(Y, P.cg, w0, w1, w2, b0a[0], kk, Z);
#pragma unroll
        for (int m = 0; m < 9; ++m) g_Za[(size_t)e * 9 + m] = Z[m];
    }
    {
        float w0[3] = {w0b[0], w0b[1], w0b[2]};
        float w1[4] = {w1b[0], w1b[1], w1b[2], w1b[3]};
        float w2[4] = {w2b[0], w2b[1], w2b[2], w2b[3]};
        float kk[3] = {kb[0], kb[1], kb[2]};
        selfmix1(Y, P.cg, w0, w1, w2, b0b[0], kk, Z);
#pragma unroll
        for (int m = 0; m < 9; ++m) g_Zb[(size_t)e * 9 + m] = Z[m];
    }
}

// ---------------------------------------------------------------------------
// Kernel 2: fused main edge kernel. Warp = EPW edges, lane = channel.
// ---------------------------------------------------------------------------
#define EPW    2
#define TPB    256
#define NWARPS 8
#define SM_WDA 0
#define SM_WDB 3072
#define SM_CG  14336
#define SM_ST  14700                       // 16B-aligned staging base
#define SM_FLOATS (SM_ST + NWARPS * 288)   // 17004 floats = 68016 B

__device__ __forceinline__ void red_add_v4(float4* addr, float4 v) {
    asm volatile("red.global.add.v4.f32 [%0], {%1,%2,%3,%4};"
                 :: "l"(addr), "f"(v.x), "f"(v.y), "f"(v.z), "f"(v.w)
                 : "memory");
}

__global__ void __launch_bounds__(TPB, 2)
edge_kernel(const float* __restrict__ nodes_snd, const int* __restrict__ edge_ind,
            const float* __restrict__ dist,
            const float* __restrict__ WdA, const float* __restrict__ bdA,
            const float* __restrict__ WdB, const float* __restrict__ bdB,
            const float* __restrict__ cmWa, const float* __restrict__ cmba,
            const float* __restrict__ cmWb, const float* __restrict__ cmbb,
            float* __restrict__ out, int E, CGParams P) {
    extern __shared__ float sm[];
    float* sWdA = sm + SM_WDA;   // [32][96]
    float* sWdB = sm + SM_WDB;   // [32][352]
    float* sCG  = sm + SM_CG;    // [363]
    float* sSt  = sm + SM_ST;    // [NWARPS][288]

    const int tid = threadIdx.x, lane = tid & 31, warp = tid >> 5;

    for (int i = tid; i < 3072;  i += TPB) sWdA[i] = WdA[i];
    for (int i = tid; i < 11264; i += TPB) sWdB[i] = WdB[i];
    for (int i = tid; i < 363;   i += TPB) sCG[i]  = P.cg[i];

    // Per-lane (channel) constants
    float bdAr[3], bdBr[11], cma[3], cmbv[3];
#pragma unroll
    for (int l = 0; l < 3; ++l) {
        bdAr[l] = bdA[lane * 3 + l];
        cma[l]  = cmWa[l * 32 + lane];
        cmbv[l] = cmWb[l * 32 + lane];
    }
#pragma unroll
    for (int j = 0; j < 11; ++j) bdBr[j] = bdB[lane * 11 + j];
    const float cba = cmba[lane], cbb = cmbb[lane];
    __syncthreads();

    const int e0 = (blockIdx.x * NWARPS + warp) * EPW;
    if (e0 >= E) return;

    float d[EPW];
#pragma unroll
    for (int k = 0; k < EPW; ++k) {
        int e = e0 + k;
        d[k] = (e < E) ? dist[(size_t)e * 32 + lane] : 0.f;
    }

    float accA[EPW][3], accB[EPW][11];
#pragma unroll
    for (int k = 0; k < EPW; ++k) {
#pragma unroll
        for (int l = 0; l < 3; ++l) accA[k][l] = 0.f;
#pragma unroll
        for (int j = 0; j < 11; ++j) accB[k][j] = 0.f;
    }

    // dist @ Wd: smem column strides 3 / 11 are coprime to 32 -> conflict-free
#pragma unroll 4
    for (int f = 0; f < 32; ++f) {
        float wA[3], wB[11];
#pragma unroll
        for (int l = 0; l < 3; ++l)  wA[l] = sWdA[f * 96 + lane * 3 + l];
#pragma unroll
        for (int j = 0; j < 11; ++j) wB[j] = sWdB[f * 352 + lane * 11 + j];
#pragma unroll
        for (int k = 0; k < EPW; ++k) {
            float df = __shfl_sync(0xffffffffu, d[k], f);
#pragma unroll
            for (int l = 0; l < 3; ++l)  accA[k][l] = fmaf(df, wA[l], accA[k][l]);
#pragma unroll
            for (int j = 0; j < 11; ++j) accB[k][j] = fmaf(df, wB[j], accB[k][j]);
        }
    }

    float* st = sSt + warp * 288;
#pragma unroll 1
    for (int k = 0; k < EPW; ++k) {
        const int e = e0 + k;
        if (e >= E) break;
        const int2 ei = reinterpret_cast<const int2*>(edge_ind)[e];
        const int snd = ei.x, rcv = ei.y;

        const float* nr = nodes_snd + ((size_t)snd * 32 + lane) * 9;
        float n[9];
#pragma unroll
        for (int m = 0; m < 9; ++m) n[m] = nr[m];

        float Za[9], Zb[9];
#pragma unroll
        for (int m = 0; m < 9; ++m) {
            Za[m] = g_Za[(size_t)e * 9 + m];
            Zb[m] = g_Zb[(size_t)e * 9 + m];
        }

        // Channel mix (cin = 1): Y[c,m] = Z[m]*W[l(m)][c] (+bias at l=0)
        float Ya[9], Yb[9];
        Ya[0] = fmaf(Za[0], cma[0], cba);
        Yb[0] = fmaf(Zb[0], cmbv[0], cbb);
#pragma unroll
        for (int m = 1; m < 4; ++m) { Ya[m] = Za[m] * cma[1]; Yb[m] = Zb[m] * cmbv[1]; }
#pragma unroll
        for (int m = 4; m < 9; ++m) { Ya[m] = Za[m] * cma[2]; Yb[m] = Zb[m] * cmbv[2]; }

        float wa[3];
#pragma unroll
        for (int l = 0; l < 3; ++l) wa[l] = (accA[k][l] + bdAr[l]) * n[0];
        float wb[11];
#pragma unroll
        for (int j = 0; j < 11; ++j) wb[j] = accB[k][j] + bdBr[j];

        // a-branch message
        float msg[9];
        msg[0] = wa[0] * Ya[0];
#pragma unroll
        for (int m = 1; m < 4; ++m) msg[m] = wa[1] * Ya[m];
#pragma unroll
        for (int m = 4; m < 9; ++m) msg[m] = wa[2] * Ya[m];

        // b-branch: pair_mix(neighbors, Yb, wb), accumulated on top
        tp_acc<0, 0, 0>(n,     Yb,     sCG + O000, wb[0]  * CN0, msg);
        tp_acc<1, 1, 0>(n + 1, Yb + 1, sCG + O110, wb[1]  * CN0, msg);
        tp_acc<2, 2, 0>(n + 4, Yb + 4, sCG + O220, wb[2]  * CN0, msg);
        tp_acc<0, 1, 1>(n,     Yb + 1, sCG + O011, wb[3]  * CN1, msg + 1);
        tp_acc<1, 0, 1>(n + 1, Yb,     sCG + O101, wb[4]  * CN1, msg + 1);
        tp_acc<1, 2, 1>(n + 1, Yb + 4, sCG + O121, wb[5]  * CN1, msg + 1);
        tp_acc<2, 1, 1>(n + 4, Yb + 1, sCG + O211, wb[6]  * CN1, msg + 1);
        tp_acc<0, 2, 2>(n,     Yb + 4, sCG + O022, wb[7]  * CN2, msg + 4);
        tp_acc<1, 1, 2>(n + 1, Yb + 1, sCG + O112, wb[8]  * CN2, msg + 4);
        tp_acc<2, 0, 2>(n + 4, Yb,     sCG + O202, wb[9]  * CN2, msg + 4);
        tp_acc<2, 2, 2>(n + 4, Yb + 4, sCG + O222, wb[10] * CN2, msg + 4);

        // Transpose via smem, then coalesced float4 vector atomics.
        // Row base rcv*288 floats = 1152 B -> 128B-aligned.
#pragma unroll
        for (int m = 0; m < 9; ++m) st[lane * 9 + m] = msg[m];
        __syncwarp();
        float4* dst = reinterpret_cast<float4*>(out + (size_t)rcv * 288);
        const float4* sv = reinterpret_cast<const float4*>(st);
        red_add_v4(dst + lane, sv[lane]);
        red_add_v4(dst + 32 + lane, sv[32 + lane]);
        if (lane < 8) red_add_v4(dst + 64 + lane, sv[64 + lane]);
        __syncwarp();
    }
}

// ---------------------------------------------------------------------------
// Host: exact double-precision port of the reference real-CG construction
// ---------------------------------------------------------------------------
typedef std::complex<double> cd;

static double factd(int n) { double r = 1.0; for (int i = 2; i <= n; ++i) r *= i; return r; }

static double w3j_h(int j1, int j2, int j3, int m1, int m2, int m3) {
    if (m1 + m2 + m3 != 0) return 0.0;
    int lo = j1 - j2; if (lo < 0) lo = -lo;
    if (j3 < lo || j3 > j1 + j2) return 0.0;
    int t1 = j2 - m1 - j3, t2 = j1 + m2 - j3, t3 = j1 + j2 - j3;
    int t4 = j1 - m1, t5 = j2 + m2;
    int tmin = 0; if (t1 > tmin) tmin = t1; if (t2 > tmin) tmin = t2;
    int tmax = t3; if (t4 < tmax) tmax = t4; if (t5 < tmax) tmax = t5;
    double s = 0.0;
    for (int t = tmin; t <= tmax; ++t)
        s += ((t & 1) ? -1.0 : 1.0) /
             (factd(t) * factd(t - t1) * factd(t - t2) *
              factd(t3 - t) * factd(t4 - t) * factd(t5 - t));
    double delta = factd(j1 + j2 - j3) * factd(j1 - j2 + j3) *
                   factd(-j1 + j2 + j3) / factd(j1 + j2 + j3 + 1);
    double norm = sqrt(delta * factd(j1 + m1) * factd(j1 - m1) *
                       factd(j2 + m2) * factd(j2 - m2) *
                       factd(j3 + m3) * factd(j3 - m3));
    int e = j1 - j2 - m3;
    double sgn = (((e % 2) + 2) % 2) ? -1.0 : 1.0;
    return sgn * norm * s;
}

static void u_real_h(int l, cd U[5][5]) {
    for (int i = 0; i < 5; ++i)
        for (int j = 0; j < 5; ++j) U[i][j] = 0.0;
    U[l][l] = 1.0;
    double s2 = 1.0 / sqrt(2.0);
    for (int m = 1; m <= l; ++m) {
        double sg = (m & 1) ? -1.0 : 1.0;
        U[l + m][l + m] = sg * s2;
        U[l + m][l - m] = s2;
        U[l - m][l + m] = cd(0.0, -1.0) * sg * s2;
        U[l - m][l - m] = cd(0.0, 1.0) * s2;
    }
}

static void real_cg_h(int l1, int l2, int l3, float* out) {
    int d1 = 2 * l1 + 1, d2 = 2 * l2 + 1, d3 = 2 * l3 + 1;
    static cd W[5][5][5];
    for (int a = 0; a < 5; ++a)
        for (int b = 0; b < 5; ++b)
            for (int c = 0; c < 5; ++c) W[a][b][c] = 0.0;
    for (int m1 = -l1; m1 <= l1; ++m1)
        for (int m2 = -l2; m2 <= l2; ++m2) {
            int m3 = -(m1 + m2);
            if (m3 >= -l3 && m3 <= l3)
                W[l1 + m1][l2 + m2][l3 + m3] = w3j_h(l1, l2, l3, m1, m2, m3);
        }
    cd U1[5][5], U2[5][5], U3[5][5];
    u_real_h(l1, U1); u_real_h(l2, U2); u_real_h(l3, U3);
    static cd T[5][5][5];
    double mxr = 0.0, mxi = 0.0;
    for (int a = 0; a < d1; ++a)
        for (int b = 0; b < d2; ++b)
            for (int c = 0; c < d3; ++c) {
                cd s = 0.0;
                for (int m = 0; m < d1; ++m) {
                    if (U1[a][m] == cd(0.0)) continue;
                    for (int n = 0; n < d2; ++n) {
                        if (U2[b][n] == cd(0.0)) continue;
                        for (int o = 0; o < d3; ++o)
                            s += U1[a][m] * U2[b][n] * U3[c][o] * W[m][n][o];
                    }
                }
                T[a][b][c] = s;
                if (fabs(s.real()) > mxr) mxr = fabs(s.real());
                if (fabs(s.imag()) > mxi) mxi = fabs(s.imag());
            }
    bool useRe = (mxr >= mxi);
    for (int a = 0; a < d1; ++a)
        for (int b = 0; b < d2; ++b)
            for (int c = 0; c < d3; ++c)
                out[(a * d2 + b) * d3 + c] =
                    (float)(useRe ? T[a][b][c].real() : T[a][b][c].imag());
}

static void build_cg(CGParams* P) {
    const int pl[11][3] = {{0,0,0},{1,1,0},{2,2,0},
                           {0,1,1},{1,0,1},{1,2,1},{2,1,1},
                           {0,2,2},{1,1,2},{2,0,2},{2,2,2}};
    int off = 0;
    for (int p = 0; p < 11; ++p) {
        int l1 = pl[p][0], l2 = pl[p][1], l3 = pl[p][2];
        real_cg_h(l1, l2, l3, P->cg + off);
        off += (2 * l1 + 1) * (2 * l2 + 1) * (2 * l3 + 1);
    }
}

// ---------------------------------------------------------------------------
// kernel_launch
// ---------------------------------------------------------------------------
extern "C" void kernel_launch(void* const* d_in, const int* in_sizes, int n_in,
                              void* d_out, int out_size) {
    CGParams P;
    build_cg(&P);

    const float* nodes_rec = (const float*)d_in[0];
    const float* nodes_snd = (const float*)d_in[1];
    const int*   edge_ind  = (const int*)d_in[2];
    const float* Y_edge    = (const float*)d_in[3];
    const float* dist      = (const float*)d_in[4];
    const int E = in_sizes[2] / 2;

    // Detect parameter ordering: signature order has Wd_a (3072) at index 12;
    // setup_inputs dict order has sm_b_w0 (3) there.
    int iA0, iB0, iWdA, ibdA, iWdB, ibdB;
    if (in_sizes[12] >= 3000) {  // signature order
        iA0 = 5;  iWdA = 12; ibdA = 13;
        iB0 = 14; iWdB = 21; ibdB = 22;
    } else {                     // dict order
        iA0 = 5;  iB0 = 12;
        iWdA = 19; ibdA = 20; iWdB = 21; ibdB = 22;
    }
    const float* sm_a_w0 = (const float*)d_in[iA0 + 0];
    const float* sm_a_w1 = (const float*)d_in[iA0 + 1];
    const float* sm_a_w2 = (const float*)d_in[iA0 + 2];
    const float* sm_a_b0 = (const float*)d_in[iA0 + 3];
    const float* sm_a_k  = (const float*)d_in[iA0 + 4];
    const float* cm_a_W  = (const float*)d_in[iA0 + 5];
    const float* cm_a_b  = (const float*)d_in[iA0 + 6];
    const float* sm_b_w0 = (const float*)d_in[iB0 + 0];
    const float* sm_b_w1 = (const float*)d_in[iB0 + 1];
    const float* sm_b_w2 = (const float*)d_in[iB0 + 2];
    const float* sm_b_b0 = (const float*)d_in[iB0 + 3];
    const float* sm_b_k  = (const float*)d_in[iB0 + 4];
    const float* cm_b_W  = (const float*)d_in[iB0 + 5];
    const float* cm_b_b  = (const float*)d_in[iB0 + 6];
    const float* Wd_a    = (const float*)d_in[iWdA];
    const float* bd_a    = (const float*)d_in[ibdA];
    const float* Wd_b    = (const float*)d_in[iWdB];
    const float* bd_b    = (const float*)d_in[ibdB];

    float* out = (float*)d_out;

    // out starts as nodes_rec; atomics accumulate messages on top.
    cudaMemcpyAsync(out, nodes_rec, (size_t)out_size * sizeof(float),
                    cudaMemcpyDeviceToDevice, 0);

    zprep_kernel<<<(E + 255) / 256, 256, 0, 0>>>(
        Y_edge, sm_a_w0, sm_a_w1, sm_a_w2, sm_a_b0, sm_a_k,
        sm_b_w0, sm_b_w1, sm_b_w2, sm_b_b0, sm_b_k, E, P);

    static bool attr_set = false;
    if (!attr_set) {
        cudaFuncSetAttribute(edge_kernel,
                             cudaFuncAttributeMaxDynamicSharedMemorySize,
                             SM_FLOATS * 4);
        attr_set = true;
    }
    int blocks = (E + NWARPS * EPW - 1) / (NWARPS * EPW);
    edge_kernel<<<blocks, TPB, SM_FLOATS * 4, 0>>>(
        nodes_snd, edge_ind, dist,
        Wd_a, bd_a, Wd_b, bd_b,
        cm_a_W, cm_a_b, cm_b_W, cm_b_b,
        out, E, P);
}

// round 10
// speedup vs baseline: 1.0087x; 1.0087x over previous
#include <cuda_runtime.h>
#include <math.h>
#include <complex>

// ---------------------------------------------------------------------------
// Problem constants
// ---------------------------------------------------------------------------
#define MAX_E 256000

// Flat CG storage, row-major (a*(2l2+1)+b)*(2l3+1)+c, 11 paths concatenated.
struct CGParams { float cg[363]; };

#define O000 0
#define O110 1
#define O220 10
#define O011 35
#define O101 44
#define O121 53
#define O211 98
#define O022 143
#define O112 168
#define O202 213
#define O222 238

// Per-edge selfmix scratch, padded to 12 floats/edge for float4 access.
__device__ float4 g_Za[MAX_E * 3];
__device__ float4 g_Zb[MAX_E * 3];

// sqrt(2*l3+1)/sqrt(npaths(l3))
#define CN0 0.57735026918962576f
#define CN1 0.86602540378443865f
#define CN2 1.11803398874989485f

__device__ __forceinline__ int muv(int i, int L) { return i < L ? L - i : i - L; }

// z[c] += w * sum_{a,b} cg[a,b,c] * x[a] * y[b], compile-time sparsity guard
// (real-CG nonzeros satisfy mu_c in {mu_a+mu_b, |mu_a-mu_b|}).
template <int L1, int L2, int L3>
__device__ __forceinline__ void tp_acc(const float* x, const float* y,
                                       const float* cg, float w, float* z) {
    float zp[2 * L3 + 1];
#pragma unroll
    for (int c = 0; c < 2 * L3 + 1; ++c) zp[c] = 0.f;
#pragma unroll
    for (int a = 0; a < 2 * L1 + 1; ++a) {
#pragma unroll
        for (int b = 0; b < 2 * L2 + 1; ++b) {
            float p = x[a] * y[b];
#pragma unroll
            for (int c = 0; c < 2 * L3 + 1; ++c) {
                const int mua = muv(a, L1), mub = muv(b, L2), muc = muv(c, L3);
                const int dmu = mua > mub ? mua - mub : mub - mua;
                if (muc == mua + mub || muc == dmu)
                    zp[c] = fmaf(cg[(a * (2 * L2 + 1) + b) * (2 * L3 + 1) + c], p, zp[c]);
            }
        }
    }
#pragma unroll
    for (int c = 0; c < 2 * L3 + 1; ++c) z[c] = fmaf(w, zp[c], z[c]);
}

// Selfmix on one 9-vector (cin = 1)
__device__ __forceinline__ void selfmix1(const float* Y, const float* cg,
                                         const float* w0, const float* w1,
                                         const float* w2, float b0,
                                         const float* k, float* Z) {
#pragma unroll
    for (int m = 0; m < 9; ++m) Z[m] = 0.f;
    tp_acc<0, 0, 0>(Y,     Y,     cg + O000, w0[0] * CN0, Z);
    tp_acc<1, 1, 0>(Y + 1, Y + 1, cg + O110, w0[1] * CN0, Z);
    tp_acc<2, 2, 0>(Y + 4, Y + 4, cg + O220, w0[2] * CN0, Z);
    tp_acc<0, 1, 1>(Y,     Y + 1, cg + O011, w1[0] * CN1, Z + 1);
    tp_acc<1, 0, 1>(Y + 1, Y,     cg + O101, w1[1] * CN1, Z + 1);
    tp_acc<1, 2, 1>(Y + 1, Y + 4, cg + O121, w1[2] * CN1, Z + 1);
    tp_acc<2, 1, 1>(Y + 4, Y + 1, cg + O211, w1[3] * CN1, Z + 1);
    tp_acc<0, 2, 2>(Y,     Y + 4, cg + O022, w2[0] * CN2, Z + 4);
    tp_acc<1, 1, 2>(Y + 1, Y + 1, cg + O112, w2[1] * CN2, Z + 4);
    tp_acc<2, 0, 2>(Y + 4, Y,     cg + O202, w2[2] * CN2, Z + 4);
    tp_acc<2, 2, 2>(Y + 4, Y + 4, cg + O222, w2[3] * CN2, Z + 4);
    Z[0] += b0 + k[0] * Y[0];
#pragma unroll
    for (int m = 1; m < 4; ++m) Z[m] += k[1] * Y[m];
#pragma unroll
    for (int m = 4; m < 9; ++m) Z[m] += k[2] * Y[m];
}

// ---------------------------------------------------------------------------
// Kernel 1: per-edge selfmix of Y_edge, both branches (float4-padded output)
// ---------------------------------------------------------------------------
__global__ void zprep_kernel(const float* __restrict__ Y_edge,
                             const float* w0a, const float* w1a, const float* w2a,
                             const float* b0a, const float* ka,
                             const float* w0b, const float* w1b, const float* w2b,
                             const float* b0b, const float* kb,
                             int E, CGParams P) {
    int e = blockIdx.x * blockDim.x + threadIdx.x;
    if (e >= E) return;
    float Y[9];
#pragma unroll
    for (int m = 0; m < 9; ++m) Y[m] = Y_edge[(size_t)e * 9 + m];

    float Z[9];
    {
        float w0[3] = {w0a[0], w0a[1], w0a[2]};
        float w1[4] = {w1a[0], w1a[1], w1a[2], w1a[3]};
        float w2[4] = {w2a[0], w2a[1], w2a[2], w2a[3]};
        float kk[3] = {ka[0], ka[1], ka[2]};
        selfmix1(Y, P.cg, w0, w1, w2, b0a[0], kk, Z);
        g_Za[(size_t)e * 3 + 0] = make_float4(Z[0], Z[1], Z[2], Z[3]);
        g_Za[(size_t)e * 3 + 1] = make_float4(Z[4], Z[5], Z[6], Z[7]);
        g_Za[(size_t)e * 3 + 2] = make_float4(Z[8], 0.f, 0.f, 0.f);
    }
    {
        float w0[3] = {w0b[0], w0b[1], w0b[2]};
        float w1[4] = {w1b[0], w1b[1], w1b[2], w1b[3]};
        float w2[4] = {w2b[0], w2b[1], w2b[2], w2b[3]};
        float kk[3] = {kb[0], kb[1], kb[2]};
        selfmix1(Y, P.cg, w0, w1, w2, b0b[0], kk, Z);
        g_Zb[(size_t)e * 3 + 0] = make_float4(Z[0], Z[1], Z[2], Z[3]);
        g_Zb[(size_t)e * 3 + 1] = make_float4(Z[4], Z[5], Z[6], Z[7]);
        g_Zb[(size_t)e * 3 + 2] = make_float4(Z[8], 0.f, 0.f, 0.f);
    }
}

// ---------------------------------------------------------------------------
// Kernel 2: fused main edge kernel. Warp = EPW edges, lane = channel.
// ---------------------------------------------------------------------------
#define EPW    4
#define TPB    128
#define NWARPS 4
#define SM_WDA 0
#define SM_WDB 3072
#define SM_CG  14336
#define SM_ST  14704                       // 16B-aligned staging base
#define SM_FLOATS (SM_ST + NWARPS * 288)   // 15856 floats = 63424 B

__device__ __forceinline__ void red_add_v4(float4* addr, float4 v) {
    asm volatile("red.global.add.v4.f32 [%0], {%1,%2,%3,%4};"
                 :: "l"(addr), "f"(v.x), "f"(v.y), "f"(v.z), "f"(v.w)
                 : "memory");
}

__global__ void __launch_bounds__(TPB, 3)
edge_kernel(const float* __restrict__ nodes_snd, const int* __restrict__ edge_ind,
            const float* __restrict__ dist,
            const float* __restrict__ WdA, const float* __restrict__ bdA,
            const float* __restrict__ WdB, const float* __restrict__ bdB,
            const float* __restrict__ cmWa, const float* __restrict__ cmba,
            const float* __restrict__ cmWb, const float* __restrict__ cmbb,
            float* __restrict__ out, int E, CGParams P) {
    extern __shared__ float sm[];
    float* sWdA = sm + SM_WDA;   // [32][96]
    float* sWdB = sm + SM_WDB;   // [32][352]
    float* sCG  = sm + SM_CG;    // [363]
    float* sSt  = sm + SM_ST;    // [NWARPS][288]

    const int tid = threadIdx.x, lane = tid & 31, warp = tid >> 5;

    for (int i = tid; i < 3072;  i += TPB) sWdA[i] = WdA[i];
    for (int i = tid; i < 11264; i += TPB) sWdB[i] = WdB[i];
    for (int i = tid; i < 363;   i += TPB) sCG[i]  = P.cg[i];

    // Per-lane (channel) constants
    float bdAr[3], bdBr[11], cma[3], cmbv[3];
#pragma unroll
    for (int l = 0; l < 3; ++l) {
        bdAr[l] = bdA[lane * 3 + l];
        cma[l]  = cmWa[l * 32 + lane];
        cmbv[l] = cmWb[l * 32 + lane];
    }
#pragma unroll
    for (int j = 0; j < 11; ++j) bdBr[j] = bdB[lane * 11 + j];
    const float cba = cmba[lane], cbb = cmbb[lane];
    __syncthreads();

    const int e0 = (blockIdx.x * NWARPS + warp) * EPW;
    if (e0 >= E) return;

    float d[EPW];
#pragma unroll
    for (int k = 0; k < EPW; ++k) {
        int e = e0 + k;
        d[k] = (e < E) ? dist[(size_t)e * 32 + lane] : 0.f;
    }

    float accA[EPW][3], accB[EPW][11];
#pragma unroll
    for (int k = 0; k < EPW; ++k) {
#pragma unroll
        for (int l = 0; l < 3; ++l) accA[k][l] = 0.f;
#pragma unroll
        for (int j = 0; j < 11; ++j) accB[k][j] = 0.f;
    }

    // dist @ Wd: smem column strides 3 / 11 are coprime to 32 -> conflict-free.
    // Weight loads amortized over EPW=4 edges.
#pragma unroll 2
    for (int f = 0; f < 32; ++f) {
        float wA[3], wB[11];
#pragma unroll
        for (int l = 0; l < 3; ++l)  wA[l] = sWdA[f * 96 + lane * 3 + l];
#pragma unroll
        for (int j = 0; j < 11; ++j) wB[j] = sWdB[f * 352 + lane * 11 + j];
#pragma unroll
        for (int k = 0; k < EPW; ++k) {
            float df = __shfl_sync(0xffffffffu, d[k], f);
#pragma unroll
            for (int l = 0; l < 3; ++l)  accA[k][l] = fmaf(df, wA[l], accA[k][l]);
#pragma unroll
            for (int j = 0; j < 11; ++j) accB[k][j] = fmaf(df, wB[j], accB[k][j]);
        }
    }

    float*  st  = sSt + warp * 288;
    float4* st4 = reinterpret_cast<float4*>(st);

#pragma unroll 1
    for (int k = 0; k < EPW; ++k) {
        const int e = e0 + k;
        if (e >= E) break;
        const int2 ei = reinterpret_cast<const int2*>(edge_ind)[e];
        const int snd = ei.x, rcv = ei.y;

        // Cooperative coalesced node-row load (1152 B) -> smem -> per-lane read
        const float4* nb4 = reinterpret_cast<const float4*>(
            nodes_snd + (size_t)snd * 288);
        st4[lane]      = nb4[lane];
        st4[32 + lane] = nb4[32 + lane];
        if (lane < 8) st4[64 + lane] = nb4[64 + lane];
        __syncwarp();
        float n[9];
#pragma unroll
        for (int m = 0; m < 9; ++m) n[m] = st[lane * 9 + m];
        __syncwarp();

        // Uniform vector loads of selfmix scratch (lane-invariant -> broadcast)
        float Za[9], Zb[9];
        {
            float4 z0 = g_Za[(size_t)e * 3 + 0];
            float4 z1 = g_Za[(size_t)e * 3 + 1];
            float4 z2 = g_Za[(size_t)e * 3 + 2];
            Za[0] = z0.x; Za[1] = z0.y; Za[2] = z0.z; Za[3] = z0.w;
            Za[4] = z1.x; Za[5] = z1.y; Za[6] = z1.z; Za[7] = z1.w;
            Za[8] = z2.x;
            z0 = g_Zb[(size_t)e * 3 + 0];
            z1 = g_Zb[(size_t)e * 3 + 1];
            z2 = g_Zb[(size_t)e * 3 + 2];
            Zb[0] = z0.x; Zb[1] = z0.y; Zb[2] = z0.z; Zb[3] = z0.w;
            Zb[4] = z1.x; Zb[5] = z1.y; Zb[6] = z1.z; Zb[7] = z1.w;
            Zb[8] = z2.x;
        }

        // Channel mix (cin = 1): Y[c,m] = Z[m]*W[l(m)][c] (+bias at l=0)
        float Ya[9], Yb[9];
        Ya[0] = fmaf(Za[0], cma[0], cba);
        Yb[0] = fmaf(Zb[0], cmbv[0], cbb);
#pragma unroll
        for (int m = 1; m < 4; ++m) { Ya[m] = Za[m] * cma[1]; Yb[m] = Zb[m] * cmbv[1]; }
#pragma unroll
        for (int m = 4; m < 9; ++m) { Ya[m] = Za[m] * cma[2]; Yb[m] = Zb[m] * cmbv[2]; }

        float wa[3];
#pragma unroll
        for (int l = 0; l < 3; ++l) wa[l] = (accA[k][l] + bdAr[l]) * n[0];
        float wb[11];
#pragma unroll
        for (int j = 0; j < 11; ++j) wb[j] = accB[k][j] + bdBr[j];

        // a-branch message
        float msg[9];
        msg[0] = wa[0] * Ya[0];
#pragma unroll
        for (int m = 1; m < 4; ++m) msg[m] = wa[1] * Ya[m];
#pragma unroll
        for (int m = 4; m < 9; ++m) msg[m] = wa[2] * Ya[m];

        // b-branch: pair_mix(neighbors, Yb, wb), accumulated on top
        tp_acc<0, 0, 0>(n,     Yb,     sCG + O000, wb[0]  * CN0, msg);
        tp_acc<1, 1, 0>(n + 1, Yb + 1, sCG + O110, wb[1]  * CN0, msg);
        tp_acc<2, 2, 0>(n + 4, Yb + 4, sCG + O220, wb[2]  * CN0, msg);
        tp_acc<0, 1, 1>(n,     Yb + 1, sCG + O011, wb[3]  * CN1, msg + 1);
        tp_acc<1, 0, 1>(n + 1, Yb,     sCG + O101, wb[4]  * CN1, msg + 1);
        tp_acc<1, 2, 1>(n + 1, Yb + 4, sCG + O121, wb[5]  * CN1, msg + 1);
        tp_acc<2, 1, 1>(n + 4, Yb + 1, sCG + O211, wb[6]  * CN1, msg + 1);
        tp_acc<0, 2, 2>(n,     Yb + 4, sCG + O022, wb[7]  * CN2, msg + 4);
        tp_acc<1, 1, 2>(n + 1, Yb + 1, sCG + O112, wb[8]  * CN2, msg + 4);
        tp_acc<2, 0, 2>(n + 4, Yb,     sCG + O202, wb[9]  * CN2, msg + 4);
        tp_acc<2, 2, 2>(n + 4, Yb + 4, sCG + O222, wb[10] * CN2, msg + 4);

        // Transpose via smem, then coalesced float4 vector atomics.
        // Row base rcv*288 floats = 1152 B -> 128B-aligned.
#pragma unroll
        for (int m = 0; m < 9; ++m) st[lane * 9 + m] = msg[m];
        __syncwarp();
        float4* dst = reinterpret_cast<float4*>(out + (size_t)rcv * 288);
        red_add_v4(dst + lane,      st4[lane]);
        red_add_v4(dst + 32 + lane, st4[32 + lane]);
        if (lane < 8) red_add_v4(dst + 64 + lane, st4[64 + lane]);
        __syncwarp();
    }
}

// ---------------------------------------------------------------------------
// Host: exact double-precision port of the reference real-CG construction
// ---------------------------------------------------------------------------
typedef std::complex<double> cd;

static double factd(int n) { double r = 1.0; for (int i = 2; i <= n; ++i) r *= i; return r; }

static double w3j_h(int j1, int j2, int j3, int m1, int m2, int m3) {
    if (m1 + m2 + m3 != 0) return 0.0;
    int lo = j1 - j2; if (lo < 0) lo = -lo;
    if (j3 < lo || j3 > j1 + j2) return 0.0;
    int t1 = j2 - m1 - j3, t2 = j1 + m2 - j3, t3 = j1 + j2 - j3;
    int t4 = j1 - m1, t5 = j2 + m2;
    int tmin = 0; if (t1 > tmin) tmin = t1; if (t2 > tmin) tmin = t2;
    int tmax = t3; if (t4 < tmax) tmax = t4; if (t5 < tmax) tmax = t5;
    double s = 0.0;
    for (int t = tmin; t <= tmax; ++t)
        s += ((t & 1) ? -1.0 : 1.0) /
             (factd(t) * factd(t - t1) * factd(t - t2) *
              factd(t3 - t) * factd(t4 - t) * factd(t5 - t));
    double delta = factd(j1 + j2 - j3) * factd(j1 - j2 + j3) *
                   factd(-j1 + j2 + j3) / factd(j1 + j2 + j3 + 1);
    double norm = sqrt(delta * factd(j1 + m1) * factd(j1 - m1) *
                       factd(j2 + m2) * factd(j2 - m2) *
                       factd(j3 + m3) * factd(j3 - m3));
    int e = j1 - j2 - m3;
    double sgn = (((e % 2) + 2) % 2) ? -1.0 : 1.0;
    return sgn * norm * s;
}

static void u_real_h(int l, cd U[5][5]) {
    for (int i = 0; i < 5; ++i)
        for (int j = 0; j < 5; ++j) U[i][j] = 0.0;
    U[l][l] = 1.0;
    double s2 = 1.0 / sqrt(2.0);
    for (int m = 1; m <= l; ++m) {
        double sg = (m & 1) ? -1.0 : 1.0;
        U[l + m][l + m] = sg * s2;
        U[l + m][l - m] = s2;
        U[l - m][l + m] = cd(0.0, -1.0) * sg * s2;
        U[l - m][l - m] = cd(0.0, 1.0) * s2;
    }
}

static void real_cg_h(int l1, int l2, int l3, float* out) {
    int d1 = 2 * l1 + 1, d2 = 2 * l2 + 1, d3 = 2 * l3 + 1;
    static cd W[5][5][5];
    for (int a = 0; a < 5; ++a)
        for (int b = 0; b < 5; ++b)
            for (int c = 0; c < 5; ++c) W[a][b][c] = 0.0;
    for (int m1 = -l1; m1 <= l1; ++m1)
        for (int m2 = -l2; m2 <= l2; ++m2) {
            int m3 = -(m1 + m2);
            if (m3 >= -l3 && m3 <= l3)
                W[l1 + m1][l2 + m2][l3 + m3] = w3j_h(l1, l2, l3, m1, m2, m3);
        }
    cd U1[5][5], U2[5][5], U3[5][5];
    u_real_h(l1, U1); u_real_h(l2, U2); u_real_h(l3, U3);
    static cd T[5][5][5];
    double mxr = 0.0, mxi = 0.0;
    for (int a = 0; a < d1; ++a)
        for (int b = 0; b < d2; ++b)
            for (int c = 0; c < d3; ++c) {
                cd s = 0.0;
                for (int m = 0; m < d1; ++m) {
                    if (U1[a][m] == cd(0.0)) continue;
                    for (int n = 0; n < d2; ++n) {
                        if (U2[b][n] == cd(0.0)) continue;
                        for (int o = 0; o < d3; ++o)
                            s += U1[a][m] * U2[b][n] * U3[c][o] * W[m][n][o];
                    }
                }
                T[a][b][c] = s;
                if (fabs(s.real()) > mxr) mxr = fabs(s.real());
                if (fabs(s.imag()) > mxi) mxi = fabs(s.imag());
            }
    bool useRe = (mxr >= mxi);
    for (int a = 0; a < d1; ++a)
        for (int b = 0; b < d2; ++b)
            for (int c = 0; c < d3; ++c)
                out[(a * d2 + b) * d3 + c] =
                    (float)(useRe ? T[a][b][c].real() : T[a][b][c].imag());
}

static void build_cg(CGParams* P) {
    const int pl[11][3] = {{0,0,0},{1,1,0},{2,2,0},
                           {0,1,1},{1,0,1},{1,2,1},{2,1,1},
                           {0,2,2},{1,1,2},{2,0,2},{2,2,2}};
    int off = 0;
    for (int p = 0; p < 11; ++p) {
        int l1 = pl[p][0], l2 = pl[p][1], l3 = pl[p][2];
        real_cg_h(l1, l2, l3, P->cg + off);
        off += (2 * l1 + 1) * (2 * l2 + 1) * (2 * l3 + 1);
    }
}

// ---------------------------------------------------------------------------
// kernel_launch
// ---------------------------------------------------------------------------
extern "C" void kernel_launch(void* const* d_in, const int* in_sizes, int n_in,
                              void* d_out, int out_size) {
    CGParams P;
    build_cg(&P);

    const float* nodes_rec = (const float*)d_in[0];
    const float* nodes_snd = (const float*)d_in[1];
    const int*   edge_ind  = (const int*)d_in[2];
    const float* Y_edge    = (const float*)d_in[3];
    const float* dist      = (const float*)d_in[4];
    const int E = in_sizes[2] / 2;

    // Detect parameter ordering: signature order has Wd_a (3072) at index 12;
    // setup_inputs dict order has sm_b_w0 (3) there.
    int iA0, iB0, iWdA, ibdA, iWdB, ibdB;
    if (in_sizes[12] >= 3000) {  // signature order
        iA0 = 5;  iWdA = 12; ibdA = 13;
        iB0 = 14; iWdB = 21; ibdB = 22;
    } else {                     // dict order
        iA0 = 5;  iB0 = 12;
        iWdA = 19; ibdA = 20; iWdB = 21; ibdB = 22;
    }
    const float* sm_a_w0 = (const float*)d_in[iA0 + 0];
    const float* sm_a_w1 = (const float*)d_in[iA0 + 1];
    const float* sm_a_w2 = (const float*)d_in[iA0 + 2];
    const float* sm_a_b0 = (const float*)d_in[iA0 + 3];
    const float* sm_a_k  = (const float*)d_in[iA0 + 4];
    const float* cm_a_W  = (const float*)d_in[iA0 + 5];
    const float* cm_a_b  = (const float*)d_in[iA0 + 6];
    const float* sm_b_w0 = (const float*)d_in[iB0 + 0];
    const float* sm_b_w1 = (const float*)d_in[iB0 + 1];
    const float* sm_b_w2 = (const float*)d_in[iB0 + 2];
    const float* sm_b_b0 = (const float*)d_in[iB0 + 3];
    const float* sm_b_k  = (const float*)d_in[iB0 + 4];
    const float* cm_b_W  = (const float*)d_in[iB0 + 5];
    const float* cm_b_b  = (const float*)d_in[iB0 + 6];
    const float* Wd_a    = (const float*)d_in[iWdA];
    const float* bd_a    = (const float*)d_in[ibdA];
    const float* Wd_b    = (const float*)d_in[iWdB];
    const float* bd_b    = (const float*)d_in[ibdB];

    float* out = (float*)d_out;

    // out starts as nodes_rec; atomics accumulate messages on top.
    cudaMemcpyAsync(out, nodes_rec, (size_t)out_size * sizeof(float),
                    cudaMemcpyDeviceToDevice, 0);

    zprep_kernel<<<(E + 255) / 256, 256, 0, 0>>>(
        Y_edge, sm_a_w0, sm_a_w1, sm_a_w2, sm_a_b0, sm_a_k,
        sm_b_w0, sm_b_w1, sm_b_w2, sm_b_b0, sm_b_k, E, P);

    static bool attr_set = false;
    if (!attr_set) {
        cudaFuncSetAttribute(edge_kernel,
                             cudaFuncAttributeMaxDynamicSharedMemorySize,
                             SM_FLOATS * 4);
        attr_set = true;
    }
    int blocks = (E + NWARPS * EPW - 1) / (NWARPS * EPW);
    edge_kernel<<<blocks, TPB, SM_FLOATS * 4, 0>>>(
        nodes_snd, edge_ind, dist,
        Wd_a, bd_a, Wd_b, bd_b,
        cm_a_W, cm_a_b, cm_b_W, cm_b_b,
        out, E, P);
}